// round 15
// baseline (speedup 1.0000x reference)
#include <cuda_runtime.h>
#include <cuda_fp16.h>
#include <cstdint>

namespace {

constexpr int Bc = 2, Hc = 12, Sc = 2048, Dc = 64;
constexpr int BM = 128;          // q rows per CTA (16 per warp)
constexpr int BN = 32;           // keys per tile
constexpr int NT = 256;          // 8 warps
constexpr int NTILE = Sc / BN;   // 64
constexpr int NSTAGE = 5;
constexpr int PITCHW = 36;       // smem row pitch in words (144 B)
constexpr int WBUF = BN * PITCHW;        // 1152 words per K/V region
constexpr int GBUFT = 1024 + 1152;       // gmem words per tile: K dense 32w + V 36w rows
constexpr int STAGE_BYTES = 2 * WBUF * 4;  // 9216
// fold 1/sqrt(64) AND log2(e) into Q: S comes out of the MMA in log2 domain.
constexpr float QSCALE = 0.125f * 1.44269504f;
constexpr float NEGB = -30000.0f;        // masked score -> ex2 == 0
// M0 = 0: p = e^s stays fp16-normal (R5 failed on denormal quantization)

__device__ uint32_t g_mask_bits[(size_t)Bc * Sc * (Sc / 32)];     // 1 MB
__device__ uint32_t g_kv[(size_t)Bc * Hc * NTILE * GBUFT];        // ~13.4 MB

// ---- helpers ----
__device__ __forceinline__ uint32_t smem_u32(const void* p) {
    uint32_t a;
    asm("{ .reg .u64 t; cvta.to.shared.u64 t, %1; cvt.u32.u64 %0, t; }" : "=r"(a) : "l"(p));
    return a;
}
__device__ __forceinline__ void cp_async16(uint32_t dst, const void* src) {
    asm volatile("cp.async.cg.shared.global [%0], [%1], 16;" :: "r"(dst), "l"(src));
}
#define CP_COMMIT() asm volatile("cp.async.commit_group;" ::: "memory")
#define CP_WAIT0()  asm volatile("cp.async.wait_group 0;" ::: "memory")
#define CP_WAIT1()  asm volatile("cp.async.wait_group 1;" ::: "memory")
#define CP_WAIT2()  asm volatile("cp.async.wait_group 2;" ::: "memory")
#define CP_WAIT3()  asm volatile("cp.async.wait_group 3;" ::: "memory")

__device__ __forceinline__ void mma_f16(float* d, const uint32_t* a, uint32_t b0, uint32_t b1) {
    asm volatile(
        "mma.sync.aligned.m16n8k16.row.col.f32.f16.f16.f32 "
        "{%0,%1,%2,%3},{%4,%5,%6,%7},{%8,%9},{%0,%1,%2,%3};"
        : "+f"(d[0]), "+f"(d[1]), "+f"(d[2]), "+f"(d[3])
        : "r"(a[0]), "r"(a[1]), "r"(a[2]), "r"(a[3]), "r"(b0), "r"(b1));
}
__device__ __forceinline__ void mma_f16_z(float* d, const uint32_t* a, uint32_t b0, uint32_t b1) {
    asm volatile(
        "mma.sync.aligned.m16n8k16.row.col.f32.f16.f16.f32 "
        "{%0,%1,%2,%3},{%4,%5,%6,%7},{%8,%9},{%10,%11,%12,%13};"
        : "=f"(d[0]), "=f"(d[1]), "=f"(d[2]), "=f"(d[3])
        : "r"(a[0]), "r"(a[1]), "r"(a[2]), "r"(a[3]), "r"(b0), "r"(b1),
          "f"(0.f), "f"(0.f), "f"(0.f), "f"(0.f));
}
__device__ __forceinline__ void ldsm_x4(uint32_t* r, uint32_t addr) {
    asm volatile("ldmatrix.sync.aligned.m8n8.x4.shared.b16 {%0,%1,%2,%3},[%4];"
                 : "=r"(r[0]), "=r"(r[1]), "=r"(r[2]), "=r"(r[3]) : "r"(addr));
}
__device__ __forceinline__ void ldsm_x4_t(uint32_t* r, uint32_t addr) {
    asm volatile("ldmatrix.sync.aligned.m8n8.x4.trans.shared.b16 {%0,%1,%2,%3},[%4];"
                 : "=r"(r[0]), "=r"(r[1]), "=r"(r[2]), "=r"(r[3]) : "r"(addr));
}
__device__ __forceinline__ void ldsm_x2_t(uint32_t* r, uint32_t addr) {
    asm volatile("ldmatrix.sync.aligned.m8n8.x2.trans.shared.b16 {%0,%1},[%2];"
                 : "=r"(r[0]), "=r"(r[1]) : "r"(addr));
}
__device__ __forceinline__ uint32_t pack_h2(float a, float b) {
    uint32_t r;
    asm("cvt.rn.f16x2.f32 %0, %1, %2;" : "=r"(r) : "f"(b), "f"(a));
    return r;
}
__device__ __forceinline__ uint32_t ex2h2(uint32_t x) {
    uint32_t r;
    asm("ex2.approx.f16x2 %0, %1;" : "=r"(r) : "r"(x));
    return r;
}

// ---- merged prep: blocks [0, KVB) convert K/V; blocks [KVB, KVB+MB) pack mask ----
constexpr int KVB = Bc * Hc * NTILE;             // 1536
constexpr int MB  = Bc * Sc * Sc / 8 / 256;      // 4096

__global__ void __launch_bounds__(256) prep_kernel(
    const float* __restrict__ K, const float* __restrict__ V, const int4* __restrict__ m)
{
    const int t = threadIdx.x;
    if (blockIdx.x < KVB) {
        const int tile = blockIdx.x;
        const int bh = tile / NTILE, kt = tile % NTILE;
        const int k0 = kt * BN;
        uint32_t* out = g_kv + (size_t)tile * GBUFT;
        const float4* K4 = reinterpret_cast<const float4*>(K) + (size_t)bh * Sc * 16;
        const float4* V4 = reinterpret_cast<const float4*>(V) + (size_t)bh * Sc * 16;
#pragma unroll
        for (int i = 0; i < 2; i++) {
            int idx = t + i * 256;
            int r = idx >> 4, c4 = idx & 15;
            int p0 = 2 * c4;
            float4 fk = K4[(size_t)(k0 + r) * 16 + c4];
            *reinterpret_cast<uint2*>(&out[r * 32 + p0]) =
                make_uint2(pack_h2(fk.x, fk.y), pack_h2(fk.z, fk.w));
            float4 fv = V4[(size_t)(k0 + r) * 16 + c4];
            *reinterpret_cast<uint2*>(&out[1024 + r * 36 + p0]) =
                make_uint2(pack_h2(fv.x, fv.y), pack_h2(fv.z, fv.w));
        }
        // V ones-column padding: col 64 = 1.0h (row-sum extractor), cols 65-71 = 0
        if (t < 32)
            *reinterpret_cast<uint4*>(&out[1024 + t * 36 + 32]) =
                make_uint4(0x00003C00u, 0u, 0u, 0u);
    } else {
        size_t i = (size_t)(blockIdx.x - KVB) * 256 + t;
        int4 a = m[2 * i], c = m[2 * i + 1];
        uint32_t byte =
            (a.x != 0 ? 1u : 0u)  | (a.y != 0 ? 2u : 0u)  | (a.z != 0 ? 4u : 0u)  | (a.w != 0 ? 8u : 0u) |
            (c.x != 0 ? 16u : 0u) | (c.y != 0 ? 32u : 0u) | (c.z != 0 ? 64u : 0u) | (c.w != 0 ? 128u : 0u);
        uint32_t x = byte << (8 * (t & 3));
        x |= __shfl_xor_sync(0xFFFFFFFFu, x, 1);
        x |= __shfl_xor_sync(0xFFFFFFFFu, x, 2);
        if ((t & 3) == 0) g_mask_bits[i >> 2] = x;
    }
}

// ---- main attention kernel: R13 body, 5-stage ring, issue 4 ahead, WAIT2 ----
__global__ void __launch_bounds__(NT, 2) attn_mma_kernel(
    const float* __restrict__ Q, float* __restrict__ Og)
{
    extern __shared__ uint32_t sTile[];

    const int t = threadIdx.x;
    const int lane = t & 31, w = t >> 5;
    const int qt = lane >> 2, qc = lane & 3;
    const int qs = 2 * qc;

    const int q0 = blockIdx.x * BM;
    const int h = blockIdx.y, b = blockIdx.z;
    const size_t bh = (size_t)b * Hc + h;
    const int qi0 = q0 + w * 16 + qt;
    const int qi1 = qi0 + 8;

    // Q A-fragments (fp16), scale*log2e folded
    uint32_t qa[4][4];
#pragma unroll
    for (int kk = 0; kk < 4; kk++) {
#pragma unroll
        for (int part = 0; part < 4; part++) {
            int row = (part & 1) ? qi1 : qi0;
            int d = kk * 16 + 2 * qc + ((part & 2) ? 8 : 0);
            const float2 f = *reinterpret_cast<const float2*>(Q + ((bh * Sc + row) << 6) + d);
            qa[kk][part] = pack_h2(f.x * QSCALE, f.y * QSCALE);
        }
    }

    float oacc[8][4];
#pragma unroll
    for (int j = 0; j < 8; j++)
#pragma unroll
        for (int i = 0; i < 4; i++) oacc[j][i] = 0.0f;
    float oaccx[4] = {0.f, 0.f, 0.f, 0.f};        // ones-column block: row sums
    float sacc[4][4];
    uint32_t pa[2][4];
    uint32_t mwa, mwb;

    const uint32_t* mrow0 = g_mask_bits + ((size_t)b * Sc + qi0) * (Sc / 32);
    const uint32_t* mrow1 = g_mask_bits + ((size_t)b * Sc + qi1) * (Sc / 32);
    const uint32_t* kvsrc = g_kv + bh * NTILE * GBUFT;
    const uint32_t sb = smem_u32(sTile);

    const int krow = ((lane >> 4) << 3) + (lane & 7);
    const int ksel = (lane >> 3) & 1;
    const int vrow = ((lane >> 3) & 1) * 8 + (lane & 7);
    const int jsel = lane >> 4;
    const uint32_t kb0 = sb + (uint32_t)(krow * PITCHW + ksel * 4) * 4;
    const uint32_t kb1 = kb0 + 16 * PITCHW * 4;
    const uint32_t vb  = sb + WBUF * 4 + (uint32_t)(vrow * PITCHW + jsel * 4) * 4;
    const uint32_t vbx = sb + WBUF * 4 + (uint32_t)((lane & 15) * PITCHW + 32) * 4;

    const uint32_t dstK  = sb + (uint32_t)((t >> 3) * PITCHW + (t & 7) * 4) * 4;
    const uint32_t dstV  = sb + WBUF * 4 + (uint32_t)t * 16;
    const uint32_t dstV2 = sb + WBUF * 4 + (uint32_t)(t + 256) * 16;

#define ISSUE(STG, ktv) do { \
    const uint32_t* _s = kvsrc + (size_t)(ktv) * GBUFT; \
    cp_async16(dstK + (STG) * STAGE_BYTES, _s + (t << 2)); \
    cp_async16(dstV + (STG) * STAGE_BYTES, _s + 1024 + (t << 2)); \
    if (t < 32) cp_async16(dstV2 + (STG) * STAGE_BYTES, _s + 1024 + ((t + 256) << 2)); \
    CP_COMMIT(); \
} while (0)

// mask-select (fp32) -> pack fp16x2 -> ex2.f16x2 : result IS the A-fragment
#define SOFTMAX() do { \
    _Pragma("unroll") \
    for (int nb = 0; nb < 4; nb++) { \
        const uint32_t _b0 = 1u << (8 * nb), _b1 = 2u << (8 * nb); \
        float s0 = (mwa & _b0) ? sacc[nb][0] : NEGB; \
        float s1 = (mwa & _b1) ? sacc[nb][1] : NEGB; \
        float s2 = (mwb & _b0) ? sacc[nb][2] : NEGB; \
        float s3 = (mwb & _b1) ? sacc[nb][3] : NEGB; \
        pa[nb >> 1][2 * (nb & 1)]     = ex2h2(pack_h2(s0, s1)); \
        pa[nb >> 1][2 * (nb & 1) + 1] = ex2h2(pack_h2(s2, s3)); \
    } \
} while (0)

#define PV_HALF(STG, kc) do { \
    const uint32_t _vb = vb + (STG) * STAGE_BYTES + (kc) * (16 * PITCHW * 4); \
    _Pragma("unroll") \
    for (int jp = 0; jp < 4; jp++) { \
        uint32_t f[4]; ldsm_x4_t(f, _vb + jp * 32); \
        mma_f16(oacc[2 * jp],     pa[kc], f[0], f[1]); \
        mma_f16(oacc[2 * jp + 1], pa[kc], f[2], f[3]); } \
    uint32_t fx[2]; \
    ldsm_x2_t(fx, vbx + (STG) * STAGE_BYTES + (kc) * (16 * PITCHW * 4)); \
    mma_f16(oaccx, pa[kc], fx[0], fx[1]); \
} while (0)

#define S_HALF(STG, jp) do { \
    const uint32_t _kb = ((jp) ? kb1 : kb0) + (STG) * STAGE_BYTES; \
    { uint32_t f[4]; ldsm_x4(f, _kb); \
      mma_f16_z(sacc[2 * (jp)],     qa[0], f[0], f[1]); \
      mma_f16_z(sacc[2 * (jp) + 1], qa[0], f[2], f[3]); } \
    _Pragma("unroll") \
    for (int kk = 1; kk < 4; kk++) { \
        uint32_t f[4]; ldsm_x4(f, _kb + kk * 32); \
        mma_f16(sacc[2 * (jp)],     qa[kk], f[0], f[1]); \
        mma_f16(sacc[2 * (jp) + 1], qa[kk], f[2], f[3]); } \
} while (0)

// interleaved PV(tile kt, stage SC) and S(tile kt+1, stage SN); issue tile kt+4
#define BODY(ktv, SC, SN, SL) do { \
    SOFTMAX(); \
    CP_WAIT2(); \
    __syncthreads(); \
    ISSUE(SL, (ktv) + 4); \
    mwa = mrow0[(ktv) + 1] >> qs; \
    mwb = mrow1[(ktv) + 1] >> qs; \
    PV_HALF(SC, 0); \
    S_HALF(SN, 0); \
    PV_HALF(SC, 1); \
    S_HALF(SN, 1); \
} while (0)

    // ---- prologue: stage 4 tiles; S(0) ----
    ISSUE(0, 0);
    ISSUE(1, 1);
    ISSUE(2, 2);
    ISSUE(3, 3);
    CP_WAIT3();
    __syncthreads();
    mwa = mrow0[0] >> qs;
    mwb = mrow1[0] >> qs;
    S_HALF(0, 0);
    S_HALF(0, 1);

    // ---- 12 x 5 pipelined bodies (kt = 0..59); body kt issues tile kt+4 <= 63 ----
    for (int kt = 0; kt < 60; kt += 5) {
        BODY(kt,     0, 1, 4);
        BODY(kt + 1, 1, 2, 0);
        BODY(kt + 2, 2, 3, 1);
        BODY(kt + 3, 3, 4, 2);
        BODY(kt + 4, 4, 0, 3);
    }

    // ---- tail bodies 60..62: no issues, no barriers (no smem writes remain) ----
    SOFTMAX();
    CP_WAIT2();
    mwa = mrow0[61] >> qs; mwb = mrow1[61] >> qs;
    PV_HALF(0, 0);  S_HALF(1, 0);
    PV_HALF(0, 1);  S_HALF(1, 1);

    SOFTMAX();
    CP_WAIT1();
    mwa = mrow0[62] >> qs; mwb = mrow1[62] >> qs;
    PV_HALF(1, 0);  S_HALF(2, 0);
    PV_HALF(1, 1);  S_HALF(2, 1);

    SOFTMAX();
    CP_WAIT0();
    mwa = mrow0[63] >> qs; mwb = mrow1[63] >> qs;
    PV_HALF(2, 0);  S_HALF(3, 0);
    PV_HALF(2, 1);  S_HALF(3, 1);

    // ---- epilogue: tile 63 (stage 3) ----
    SOFTMAX();
    PV_HALF(3, 0);
    PV_HALF(3, 1);

#undef BODY
#undef S_HALF
#undef PV_HALF
#undef SOFTMAX
#undef ISSUE

    // ---- lsum lives in ones-column block at qc==0; broadcast across quad ----
    const float l0 = __shfl_sync(0xFFFFFFFFu, oaccx[0], lane & 28);
    const float l1 = __shfl_sync(0xFFFFFFFFu, oaccx[2], lane & 28);
    const float inv0 = 1.0f / l0, inv1 = 1.0f / l1;

    float* o0 = Og + ((bh * Sc + qi0) << 6) + 2 * qc;
    float* o1 = Og + ((bh * Sc + qi1) << 6) + 2 * qc;
#pragma unroll
    for (int j = 0; j < 8; j++) {
        *reinterpret_cast<float2*>(o0 + j * 8) = make_float2(oacc[j][0] * inv0, oacc[j][1] * inv0);
        *reinterpret_cast<float2*>(o1 + j * 8) = make_float2(oacc[j][2] * inv1, oacc[j][3] * inv1);
    }
}

} // namespace

extern "C" void kernel_launch(void* const* d_in, const int* in_sizes, int n_in,
                              void* d_out, int out_size)
{
    const float* Q = (const float*)d_in[0];
    const float* K = (const float*)d_in[1];
    const float* V = (const float*)d_in[2];
    const int*   M = (const int*)d_in[3];
    float*       O = (float*)d_out;

    prep_kernel<<<KVB + MB, 256>>>(K, V, (const int4*)M);

    static int smem_set = 0;
    const int smem_bytes = NSTAGE * STAGE_BYTES;   // 46080
    if (!smem_set) {
        cudaFuncSetAttribute(attn_mma_kernel, cudaFuncAttributeMaxDynamicSharedMemorySize, smem_bytes);
        smem_set = 1;
    }
    dim3 grid(Sc / BM, Hc, Bc);
    attn_mma_kernel<<<grid, NT, smem_bytes>>>(Q, O);
}

// round 16
// speedup vs baseline: 1.4961x; 1.4961x over previous
#include <cuda_runtime.h>
#include <cuda_fp16.h>
#include <cstdint>

namespace {

constexpr int Bc = 2, Hc = 12, Sc = 2048, Dc = 64;
constexpr int BM = 128;          // q rows per CTA (16 per warp)
constexpr int BN = 32;           // keys per tile
constexpr int NT = 256;          // 8 warps
constexpr int NTILE = Sc / BN;   // 64
constexpr int NSTAGE = 4;
constexpr int PITCHW = 36;       // smem row pitch in words (144 B)
constexpr int WBUF = BN * PITCHW;        // 1152 words per K/V region
constexpr int GBUFT = 1024 + 1152;       // gmem words per tile: K dense 32w + V 36w rows
constexpr int STAGE_BYTES = 2 * WBUF * 4;
// fold 1/sqrt(64) AND log2(e) into Q: S comes out of the MMA in log2 domain.
constexpr float QSCALE = 0.125f * 1.44269504f;
constexpr float NEGB = -30000.0f;        // masked score -> ex2 == 0
// M0 = 0: p = e^s stays fp16-normal (R5 failed on denormal quantization)

__device__ uint32_t g_mask_bits[(size_t)Bc * Sc * (Sc / 32)];     // 1 MB
__device__ uint32_t g_kv[(size_t)Bc * Hc * NTILE * GBUFT];        // ~13.4 MB

// ---- helpers ----
__device__ __forceinline__ uint32_t smem_u32(const void* p) {
    uint32_t a;
    asm("{ .reg .u64 t; cvta.to.shared.u64 t, %1; cvt.u32.u64 %0, t; }" : "=r"(a) : "l"(p));
    return a;
}
__device__ __forceinline__ void cp_async16(uint32_t dst, const void* src) {
    asm volatile("cp.async.cg.shared.global [%0], [%1], 16;" :: "r"(dst), "l"(src));
}
#define CP_COMMIT() asm volatile("cp.async.commit_group;" ::: "memory")
#define CP_WAIT0()  asm volatile("cp.async.wait_group 0;" ::: "memory")
#define CP_WAIT1()  asm volatile("cp.async.wait_group 1;" ::: "memory")
#define CP_WAIT2()  asm volatile("cp.async.wait_group 2;" ::: "memory")

__device__ __forceinline__ void mma_f16(float* d, const uint32_t* a, uint32_t b0, uint32_t b1) {
    asm volatile(
        "mma.sync.aligned.m16n8k16.row.col.f32.f16.f16.f32 "
        "{%0,%1,%2,%3},{%4,%5,%6,%7},{%8,%9},{%0,%1,%2,%3};"
        : "+f"(d[0]), "+f"(d[1]), "+f"(d[2]), "+f"(d[3])
        : "r"(a[0]), "r"(a[1]), "r"(a[2]), "r"(a[3]), "r"(b0), "r"(b1));
}
__device__ __forceinline__ void mma_f16_z(float* d, const uint32_t* a, uint32_t b0, uint32_t b1) {
    asm volatile(
        "mma.sync.aligned.m16n8k16.row.col.f32.f16.f16.f32 "
        "{%0,%1,%2,%3},{%4,%5,%6,%7},{%8,%9},{%10,%11,%12,%13};"
        : "=f"(d[0]), "=f"(d[1]), "=f"(d[2]), "=f"(d[3])
        : "r"(a[0]), "r"(a[1]), "r"(a[2]), "r"(a[3]), "r"(b0), "r"(b1),
          "f"(0.f), "f"(0.f), "f"(0.f), "f"(0.f));
}
__device__ __forceinline__ void ldsm_x4(uint32_t* r, uint32_t addr) {
    asm volatile("ldmatrix.sync.aligned.m8n8.x4.shared.b16 {%0,%1,%2,%3},[%4];"
                 : "=r"(r[0]), "=r"(r[1]), "=r"(r[2]), "=r"(r[3]) : "r"(addr));
}
__device__ __forceinline__ void ldsm_x4_t(uint32_t* r, uint32_t addr) {
    asm volatile("ldmatrix.sync.aligned.m8n8.x4.trans.shared.b16 {%0,%1,%2,%3},[%4];"
                 : "=r"(r[0]), "=r"(r[1]), "=r"(r[2]), "=r"(r[3]) : "r"(addr));
}
__device__ __forceinline__ void ldsm_x2_t(uint32_t* r, uint32_t addr) {
    asm volatile("ldmatrix.sync.aligned.m8n8.x2.trans.shared.b16 {%0,%1},[%2];"
                 : "=r"(r[0]), "=r"(r[1]) : "r"(addr));
}
__device__ __forceinline__ uint32_t pack_h2(float a, float b) {
    uint32_t r;
    asm("cvt.rn.f16x2.f32 %0, %1, %2;" : "=r"(r) : "f"(b), "f"(a));
    return r;
}
__device__ __forceinline__ uint32_t ex2h2(uint32_t x) {
    uint32_t r;
    asm("ex2.approx.f16x2 %0, %1;" : "=r"(r) : "r"(x));
    return r;
}

// ---- merged prep: blocks [0, KVB) convert K/V; blocks [KVB, KVB+MB2) pack mask ----
constexpr int KVB = Bc * Hc * NTILE;             // 1536
constexpr int MB2 = Bc * Sc * Sc / 32 / 256;     // 1024 mask blocks (32 ints/thread)

__global__ void __launch_bounds__(256) prep_kernel(
    const float* __restrict__ K, const float* __restrict__ V, const int4* __restrict__ m)
{
    const int t = threadIdx.x;
    if (blockIdx.x < KVB) {
        const int tile = blockIdx.x;
        const int bh = tile / NTILE, kt = tile % NTILE;
        const int k0 = kt * BN;
        uint32_t* out = g_kv + (size_t)tile * GBUFT;
        const float4* K4 = reinterpret_cast<const float4*>(K) + (size_t)bh * Sc * 16;
        const float4* V4 = reinterpret_cast<const float4*>(V) + (size_t)bh * Sc * 16;
#pragma unroll
        for (int i = 0; i < 2; i++) {
            int idx = t + i * 256;
            int r = idx >> 4, c4 = idx & 15;
            int p0 = 2 * c4;
            float4 fk = K4[(size_t)(k0 + r) * 16 + c4];
            *reinterpret_cast<uint2*>(&out[r * 32 + p0]) =
                make_uint2(pack_h2(fk.x, fk.y), pack_h2(fk.z, fk.w));
            float4 fv = V4[(size_t)(k0 + r) * 16 + c4];
            *reinterpret_cast<uint2*>(&out[1024 + r * 36 + p0]) =
                make_uint2(pack_h2(fv.x, fv.y), pack_h2(fv.z, fv.w));
        }
        // V ones-column padding: col 64 = 1.0h (row-sum extractor), cols 65-71 = 0
        if (t < 32)
            *reinterpret_cast<uint4*>(&out[1024 + t * 36 + 32]) =
                make_uint4(0x00003C00u, 0u, 0u, 0u);
    } else {
        // 32 ints per thread -> one uint32 of mask bits, written directly
        size_t i = (size_t)(blockIdx.x - KVB) * 256 + t;   // 32-int chunk id
        const int4* src = m + 8 * i;
        uint32_t bits = 0;
#pragma unroll
        for (int g = 0; g < 8; g++) {
            int4 v = src[g];
            bits |= ((v.x != 0 ? 1u : 0u) | (v.y != 0 ? 2u : 0u) |
                     (v.z != 0 ? 4u : 0u) | (v.w != 0 ? 8u : 0u)) << (4 * g);
        }
        g_mask_bits[i] = bits;
    }
}

// ---- main attention kernel: R13 pipeline (4-stage ring, issue kt+3, WAIT1) ----
__global__ void __launch_bounds__(NT, 2) attn_mma_kernel(
    const float* __restrict__ Q, float* __restrict__ Og)
{
    extern __shared__ uint32_t sTile[];

    const int t = threadIdx.x;
    const int lane = t & 31, w = t >> 5;
    const int qt = lane >> 2, qc = lane & 3;
    const int qs = 2 * qc;

    const int q0 = blockIdx.x * BM;
    const int h = blockIdx.y, b = blockIdx.z;
    const size_t bh = (size_t)b * Hc + h;
    const int qi0 = q0 + w * 16 + qt;
    const int qi1 = qi0 + 8;

    // Q A-fragments (fp16), scale*log2e folded
    uint32_t qa[4][4];
#pragma unroll
    for (int kk = 0; kk < 4; kk++) {
#pragma unroll
        for (int part = 0; part < 4; part++) {
            int row = (part & 1) ? qi1 : qi0;
            int d = kk * 16 + 2 * qc + ((part & 2) ? 8 : 0);
            const float2 f = *reinterpret_cast<const float2*>(Q + ((bh * Sc + row) << 6) + d);
            qa[kk][part] = pack_h2(f.x * QSCALE, f.y * QSCALE);
        }
    }

    float oacc[8][4];
#pragma unroll
    for (int j = 0; j < 8; j++)
#pragma unroll
        for (int i = 0; i < 4; i++) oacc[j][i] = 0.0f;
    float oaccx[4] = {0.f, 0.f, 0.f, 0.f};        // ones-column block: row sums
    float sacc[4][4];
    uint32_t pa[2][4];
    uint32_t mwa, mwb;

    const uint32_t* mrow0 = g_mask_bits + ((size_t)b * Sc + qi0) * (Sc / 32);
    const uint32_t* mrow1 = g_mask_bits + ((size_t)b * Sc + qi1) * (Sc / 32);
    const uint32_t* kvsrc = g_kv + bh * NTILE * GBUFT;
    const uint32_t sb = smem_u32(sTile);

    const int krow = ((lane >> 4) << 3) + (lane & 7);
    const int ksel = (lane >> 3) & 1;
    const int vrow = ((lane >> 3) & 1) * 8 + (lane & 7);
    const int jsel = lane >> 4;
    const uint32_t kb0 = sb + (uint32_t)(krow * PITCHW + ksel * 4) * 4;
    const uint32_t kb1 = kb0 + 16 * PITCHW * 4;
    const uint32_t vb  = sb + WBUF * 4 + (uint32_t)(vrow * PITCHW + jsel * 4) * 4;
    const uint32_t vbx = sb + WBUF * 4 + (uint32_t)((lane & 15) * PITCHW + 32) * 4;

    const uint32_t dstK  = sb + (uint32_t)((t >> 3) * PITCHW + (t & 7) * 4) * 4;
    const uint32_t dstV  = sb + WBUF * 4 + (uint32_t)t * 16;
    const uint32_t dstV2 = sb + WBUF * 4 + (uint32_t)(t + 256) * 16;

#define ISSUE(STG, ktv) do { \
    const uint32_t* _s = kvsrc + (size_t)(ktv) * GBUFT; \
    cp_async16(dstK + (STG) * STAGE_BYTES, _s + (t << 2)); \
    cp_async16(dstV + (STG) * STAGE_BYTES, _s + 1024 + (t << 2)); \
    if (t < 32) cp_async16(dstV2 + (STG) * STAGE_BYTES, _s + 1024 + ((t + 256) << 2)); \
    CP_COMMIT(); \
} while (0)

// mask-select (fp32) -> pack fp16x2 -> ex2.f16x2 : result IS the A-fragment
#define SOFTMAX() do { \
    _Pragma("unroll") \
    for (int nb = 0; nb < 4; nb++) { \
        const uint32_t _b0 = 1u << (8 * nb), _b1 = 2u << (8 * nb); \
        float s0 = (mwa & _b0) ? sacc[nb][0] : NEGB; \
        float s1 = (mwa & _b1) ? sacc[nb][1] : NEGB; \
        float s2 = (mwb & _b0) ? sacc[nb][2] : NEGB; \
        float s3 = (mwb & _b1) ? sacc[nb][3] : NEGB; \
        pa[nb >> 1][2 * (nb & 1)]     = ex2h2(pack_h2(s0, s1)); \
        pa[nb >> 1][2 * (nb & 1) + 1] = ex2h2(pack_h2(s2, s3)); \
    } \
} while (0)

#define PV_HALF(STG, kc) do { \
    const uint32_t _vb = vb + (STG) * STAGE_BYTES + (kc) * (16 * PITCHW * 4); \
    _Pragma("unroll") \
    for (int jp = 0; jp < 4; jp++) { \
        uint32_t f[4]; ldsm_x4_t(f, _vb + jp * 32); \
        mma_f16(oacc[2 * jp],     pa[kc], f[0], f[1]); \
        mma_f16(oacc[2 * jp + 1], pa[kc], f[2], f[3]); } \
    uint32_t fx[2]; \
    ldsm_x2_t(fx, vbx + (STG) * STAGE_BYTES + (kc) * (16 * PITCHW * 4)); \
    mma_f16(oaccx, pa[kc], fx[0], fx[1]); \
} while (0)

#define S_HALF(STG, jp) do { \
    const uint32_t _kb = ((jp) ? kb1 : kb0) + (STG) * STAGE_BYTES; \
    { uint32_t f[4]; ldsm_x4(f, _kb); \
      mma_f16_z(sacc[2 * (jp)],     qa[0], f[0], f[1]); \
      mma_f16_z(sacc[2 * (jp) + 1], qa[0], f[2], f[3]); } \
    _Pragma("unroll") \
    for (int kk = 1; kk < 4; kk++) { \
        uint32_t f[4]; ldsm_x4(f, _kb + kk * 32); \
        mma_f16(sacc[2 * (jp)],     qa[kk], f[0], f[1]); \
        mma_f16(sacc[2 * (jp) + 1], qa[kk], f[2], f[3]); } \
} while (0)

// interleaved PV(tile kt, stage SC) and S(tile kt+1, stage SN)
// mask LDGs hoisted before the wait so they land under wait+barrier latency
#define BODY(ktv, SC, SN, SL, WAITM) do { \
    SOFTMAX(); \
    mwa = mrow0[(ktv) + 1] >> qs; \
    mwb = mrow1[(ktv) + 1] >> qs; \
    WAITM(); \
    __syncthreads(); \
    if ((ktv) + 3 < NTILE) ISSUE(SL, (ktv) + 3); \
    PV_HALF(SC, 0); \
    S_HALF(SN, 0); \
    PV_HALF(SC, 1); \
    S_HALF(SN, 1); \
} while (0)

    // ---- prologue: stage 3 tiles; S(0) ----
    ISSUE(0, 0);
    ISSUE(1, 1);
    ISSUE(2, 2);
    CP_WAIT2();
    __syncthreads();
    mwa = mrow0[0] >> qs;
    mwb = mrow1[0] >> qs;
    S_HALF(0, 0);
    S_HALF(0, 1);

    // ---- 15 x 4 pipelined bodies (kt = 0..59) ----
    for (int kt = 0; kt < 60; kt += 4) {
        BODY(kt,     0, 1, 3, CP_WAIT1);
        BODY(kt + 1, 1, 2, 0, CP_WAIT1);
        BODY(kt + 2, 2, 3, 1, CP_WAIT1);
        BODY(kt + 3, 3, 0, 2, CP_WAIT1);
    }
    // ---- tail bodies 60..62 ----
    BODY(60, 0, 1, 3, CP_WAIT1);
    BODY(61, 1, 2, 0, CP_WAIT1);
    BODY(62, 2, 3, 1, CP_WAIT0);     // tile 63 must be fully resident

    // ---- epilogue: tile 63 (stage 3) ----
    SOFTMAX();
    PV_HALF(3, 0);
    PV_HALF(3, 1);

#undef BODY
#undef S_HALF
#undef PV_HALF
#undef SOFTMAX
#undef ISSUE

    // ---- lsum lives in ones-column block at qc==0; broadcast across quad ----
    const float l0 = __shfl_sync(0xFFFFFFFFu, oaccx[0], lane & 28);
    const float l1 = __shfl_sync(0xFFFFFFFFu, oaccx[2], lane & 28);
    const float inv0 = 1.0f / l0, inv1 = 1.0f / l1;

    float* o0 = Og + ((bh * Sc + qi0) << 6) + 2 * qc;
    float* o1 = Og + ((bh * Sc + qi1) << 6) + 2 * qc;
#pragma unroll
    for (int j = 0; j < 8; j++) {
        *reinterpret_cast<float2*>(o0 + j * 8) = make_float2(oacc[j][0] * inv0, oacc[j][1] * inv0);
        *reinterpret_cast<float2*>(o1 + j * 8) = make_float2(oacc[j][2] * inv1, oacc[j][3] * inv1);
    }
}

} // namespace

extern "C" void kernel_launch(void* const* d_in, const int* in_sizes, int n_in,
                              void* d_out, int out_size)
{
    const float* Q = (const float*)d_in[0];
    const float* K = (const float*)d_in[1];
    const float* V = (const float*)d_in[2];
    const int*   M = (const int*)d_in[3];
    float*       O = (float*)d_out;

    prep_kernel<<<KVB + MB2, 256>>>(K, V, (const int4*)M);

    static int smem_set = 0;
    const int smem_bytes = NSTAGE * STAGE_BYTES;   // 36864
    if (!smem_set) {
        cudaFuncSetAttribute(attn_mma_kernel, cudaFuncAttributeMaxDynamicSharedMemorySize, smem_bytes);
        smem_set = 1;
    }
    dim3 grid(Sc / BM, Hc, Bc);
    attn_mma_kernel<<<grid, NT, smem_bytes>>>(Q, O);
}

// round 17
// speedup vs baseline: 1.4966x; 1.0003x over previous
#include <cuda_runtime.h>
#include <cuda_fp16.h>
#include <cstdint>

namespace {

constexpr int Bc = 2, Hc = 12, Sc = 2048, Dc = 64;
constexpr int BM = 128;          // q rows per CTA (16 per warp)
constexpr int BN = 32;           // keys per tile
constexpr int NT = 256;          // 8 warps
constexpr int NTILE = Sc / BN;   // 64
constexpr int NSTAGE = 4;
constexpr int PITCHW = 36;       // smem row pitch in words (144 B)
constexpr int WBUF = BN * PITCHW;        // 1152 words per K/V region
constexpr int GBUFT = 1024 + 1152;       // gmem words per tile: K dense 32w + V 36w rows
constexpr int STAGE_BYTES = 2 * WBUF * 4;
// fold 1/sqrt(64) AND log2(e) into Q: S comes out of the MMA in log2 domain.
constexpr float QSCALE = 0.125f * 1.44269504f;
constexpr float NEGB = -30000.0f;        // masked score -> ex2 == 0
// M0 = 0: p = e^s stays fp16-normal (R5 failed on denormal quantization)

__device__ uint32_t g_mask_bits[(size_t)Bc * Sc * (Sc / 32)];     // 1 MB
__device__ uint32_t g_kv[(size_t)Bc * Hc * NTILE * GBUFT];        // ~13.4 MB

// ---- helpers ----
__device__ __forceinline__ uint32_t smem_u32(const void* p) {
    uint32_t a;
    asm("{ .reg .u64 t; cvta.to.shared.u64 t, %1; cvt.u32.u64 %0, t; }" : "=r"(a) : "l"(p));
    return a;
}
__device__ __forceinline__ void cp_async16(uint32_t dst, const void* src) {
    asm volatile("cp.async.cg.shared.global [%0], [%1], 16;" :: "r"(dst), "l"(src));
}
#define CP_COMMIT() asm volatile("cp.async.commit_group;" ::: "memory")
#define CP_WAIT0()  asm volatile("cp.async.wait_group 0;" ::: "memory")
#define CP_WAIT1()  asm volatile("cp.async.wait_group 1;" ::: "memory")
#define CP_WAIT2()  asm volatile("cp.async.wait_group 2;" ::: "memory")

__device__ __forceinline__ void mma_f16(float* d, const uint32_t* a, uint32_t b0, uint32_t b1) {
    asm volatile(
        "mma.sync.aligned.m16n8k16.row.col.f32.f16.f16.f32 "
        "{%0,%1,%2,%3},{%4,%5,%6,%7},{%8,%9},{%0,%1,%2,%3};"
        : "+f"(d[0]), "+f"(d[1]), "+f"(d[2]), "+f"(d[3])
        : "r"(a[0]), "r"(a[1]), "r"(a[2]), "r"(a[3]), "r"(b0), "r"(b1));
}
__device__ __forceinline__ void mma_f16_z(float* d, const uint32_t* a, uint32_t b0, uint32_t b1) {
    asm volatile(
        "mma.sync.aligned.m16n8k16.row.col.f32.f16.f16.f32 "
        "{%0,%1,%2,%3},{%4,%5,%6,%7},{%8,%9},{%10,%11,%12,%13};"
        : "=f"(d[0]), "=f"(d[1]), "=f"(d[2]), "=f"(d[3])
        : "r"(a[0]), "r"(a[1]), "r"(a[2]), "r"(a[3]), "r"(b0), "r"(b1),
          "f"(0.f), "f"(0.f), "f"(0.f), "f"(0.f));
}
__device__ __forceinline__ void ldsm_x4(uint32_t* r, uint32_t addr) {
    asm volatile("ldmatrix.sync.aligned.m8n8.x4.shared.b16 {%0,%1,%2,%3},[%4];"
                 : "=r"(r[0]), "=r"(r[1]), "=r"(r[2]), "=r"(r[3]) : "r"(addr));
}
__device__ __forceinline__ void ldsm_x4_t(uint32_t* r, uint32_t addr) {
    asm volatile("ldmatrix.sync.aligned.m8n8.x4.trans.shared.b16 {%0,%1,%2,%3},[%4];"
                 : "=r"(r[0]), "=r"(r[1]), "=r"(r[2]), "=r"(r[3]) : "r"(addr));
}
__device__ __forceinline__ void ldsm_x2_t(uint32_t* r, uint32_t addr) {
    asm volatile("ldmatrix.sync.aligned.m8n8.x2.trans.shared.b16 {%0,%1},[%2];"
                 : "=r"(r[0]), "=r"(r[1]) : "r"(addr));
}
__device__ __forceinline__ uint32_t pack_h2(float a, float b) {
    uint32_t r;
    asm("cvt.rn.f16x2.f32 %0, %1, %2;" : "=r"(r) : "f"(b), "f"(a));
    return r;
}
__device__ __forceinline__ uint32_t ex2h2(uint32_t x) {
    uint32_t r;
    asm("ex2.approx.f16x2 %0, %1;" : "=r"(r) : "r"(x));
    return r;
}

// ---- merged prep: blocks [0, KVB) convert K/V; blocks [KVB, KVB+MB2) pack mask ----
constexpr int KVB = Bc * Hc * NTILE;             // 1536
constexpr int MB2 = Bc * Sc * Sc / 32 / 256;     // 1024 mask blocks (32 ints/thread)

__global__ void __launch_bounds__(256) prep_kernel(
    const float* __restrict__ K, const float* __restrict__ V, const int4* __restrict__ m)
{
    // PDL: allow the dependent (main) kernel to launch now; it synchronizes
    // on full completion of this grid before touching g_kv / g_mask_bits.
    cudaTriggerProgrammaticLaunchCompletion();

    const int t = threadIdx.x;
    if (blockIdx.x < KVB) {
        const int tile = blockIdx.x;
        const int bh = tile / NTILE, kt = tile % NTILE;
        const int k0 = kt * BN;
        uint32_t* out = g_kv + (size_t)tile * GBUFT;
        const float4* K4 = reinterpret_cast<const float4*>(K) + (size_t)bh * Sc * 16;
        const float4* V4 = reinterpret_cast<const float4*>(V) + (size_t)bh * Sc * 16;
#pragma unroll
        for (int i = 0; i < 2; i++) {
            int idx = t + i * 256;
            int r = idx >> 4, c4 = idx & 15;
            int p0 = 2 * c4;
            float4 fk = K4[(size_t)(k0 + r) * 16 + c4];
            *reinterpret_cast<uint2*>(&out[r * 32 + p0]) =
                make_uint2(pack_h2(fk.x, fk.y), pack_h2(fk.z, fk.w));
            float4 fv = V4[(size_t)(k0 + r) * 16 + c4];
            *reinterpret_cast<uint2*>(&out[1024 + r * 36 + p0]) =
                make_uint2(pack_h2(fv.x, fv.y), pack_h2(fv.z, fv.w));
        }
        // V ones-column padding: col 64 = 1.0h (row-sum extractor), cols 65-71 = 0
        if (t < 32)
            *reinterpret_cast<uint4*>(&out[1024 + t * 36 + 32]) =
                make_uint4(0x00003C00u, 0u, 0u, 0u);
    } else {
        // 32 ints per thread -> one uint32 of mask bits
        size_t i = (size_t)(blockIdx.x - KVB) * 256 + t;
        const int4* src = m + 8 * i;
        uint32_t bits = 0;
#pragma unroll
        for (int g = 0; g < 8; g++) {
            int4 v = src[g];
            bits |= ((v.x != 0 ? 1u : 0u) | (v.y != 0 ? 2u : 0u) |
                     (v.z != 0 ? 4u : 0u) | (v.w != 0 ? 8u : 0u)) << (4 * g);
        }
        g_mask_bits[i] = bits;
    }
}

// ---- main attention kernel: R13/R16 pipeline + PDL prologue overlap ----
__global__ void __launch_bounds__(NT, 2) attn_mma_kernel(
    const float* __restrict__ Q, float* __restrict__ Og)
{
    extern __shared__ uint32_t sTile[];

    const int t = threadIdx.x;
    const int lane = t & 31, w = t >> 5;
    const int qt = lane >> 2, qc = lane & 3;
    const int qs = 2 * qc;

    const int q0 = blockIdx.x * BM;
    const int h = blockIdx.y, b = blockIdx.z;
    const size_t bh = (size_t)b * Hc + h;
    const int qi0 = q0 + w * 16 + qt;
    const int qi1 = qi0 + 8;

    // --- prep-independent work first (overlaps prep under PDL) ---
    // Q A-fragments (fp16), scale*log2e folded
    uint32_t qa[4][4];
#pragma unroll
    for (int kk = 0; kk < 4; kk++) {
#pragma unroll
        for (int part = 0; part < 4; part++) {
            int row = (part & 1) ? qi1 : qi0;
            int d = kk * 16 + 2 * qc + ((part & 2) ? 8 : 0);
            const float2 f = *reinterpret_cast<const float2*>(Q + ((bh * Sc + row) << 6) + d);
            qa[kk][part] = pack_h2(f.x * QSCALE, f.y * QSCALE);
        }
    }

    float oacc[8][4];
#pragma unroll
    for (int j = 0; j < 8; j++)
#pragma unroll
        for (int i = 0; i < 4; i++) oacc[j][i] = 0.0f;
    float oaccx[4] = {0.f, 0.f, 0.f, 0.f};        // ones-column block: row sums
    float sacc[4][4];
    uint32_t pa[2][4];
    uint32_t mwa, mwb;
    uint32_t fx[2];                               // tile-invariant ones-fragment

    const uint32_t* mrow0 = g_mask_bits + ((size_t)b * Sc + qi0) * (Sc / 32);
    const uint32_t* mrow1 = g_mask_bits + ((size_t)b * Sc + qi1) * (Sc / 32);
    const uint32_t* kvsrc = g_kv + bh * NTILE * GBUFT;
    const uint32_t sb = smem_u32(sTile);

    const int krow = ((lane >> 4) << 3) + (lane & 7);
    const int ksel = (lane >> 3) & 1;
    const int vrow = ((lane >> 3) & 1) * 8 + (lane & 7);
    const int jsel = lane >> 4;
    const uint32_t kb0 = sb + (uint32_t)(krow * PITCHW + ksel * 4) * 4;
    const uint32_t kb1 = kb0 + 16 * PITCHW * 4;
    const uint32_t vb  = sb + WBUF * 4 + (uint32_t)(vrow * PITCHW + jsel * 4) * 4;
    const uint32_t vbx = sb + WBUF * 4 + (uint32_t)((lane & 15) * PITCHW + 32) * 4;

    const uint32_t dstK  = sb + (uint32_t)((t >> 3) * PITCHW + (t & 7) * 4) * 4;
    const uint32_t dstV  = sb + WBUF * 4 + (uint32_t)t * 16;
    const uint32_t dstV2 = sb + WBUF * 4 + (uint32_t)(t + 256) * 16;

    // --- wait for prep's writes (g_kv, g_mask_bits) to be visible ---
    cudaGridDependencySynchronize();

#define ISSUE(STG, ktv) do { \
    const uint32_t* _s = kvsrc + (size_t)(ktv) * GBUFT; \
    cp_async16(dstK + (STG) * STAGE_BYTES, _s + (t << 2)); \
    cp_async16(dstV + (STG) * STAGE_BYTES, _s + 1024 + (t << 2)); \
    if (t < 32) cp_async16(dstV2 + (STG) * STAGE_BYTES, _s + 1024 + ((t + 256) << 2)); \
    CP_COMMIT(); \
} while (0)

// mask-select (fp32) -> pack fp16x2 -> ex2.f16x2 : result IS the A-fragment
#define SOFTMAX() do { \
    _Pragma("unroll") \
    for (int nb = 0; nb < 4; nb++) { \
        const uint32_t _b0 = 1u << (8 * nb), _b1 = 2u << (8 * nb); \
        float s0 = (mwa & _b0) ? sacc[nb][0] : NEGB; \
        float s1 = (mwa & _b1) ? sacc[nb][1] : NEGB; \
        float s2 = (mwb & _b0) ? sacc[nb][2] : NEGB; \
        float s3 = (mwb & _b1) ? sacc[nb][3] : NEGB; \
        pa[nb >> 1][2 * (nb & 1)]     = ex2h2(pack_h2(s0, s1)); \
        pa[nb >> 1][2 * (nb & 1) + 1] = ex2h2(pack_h2(s2, s3)); \
    } \
} while (0)

#define PV_HALF(STG, kc) do { \
    const uint32_t _vb = vb + (STG) * STAGE_BYTES + (kc) * (16 * PITCHW * 4); \
    _Pragma("unroll") \
    for (int jp = 0; jp < 4; jp++) { \
        uint32_t f[4]; ldsm_x4_t(f, _vb + jp * 32); \
        mma_f16(oacc[2 * jp],     pa[kc], f[0], f[1]); \
        mma_f16(oacc[2 * jp + 1], pa[kc], f[2], f[3]); } \
    mma_f16(oaccx, pa[kc], fx[0], fx[1]); \
} while (0)

#define S_HALF(STG, jp) do { \
    const uint32_t _kb = ((jp) ? kb1 : kb0) + (STG) * STAGE_BYTES; \
    { uint32_t f[4]; ldsm_x4(f, _kb); \
      mma_f16_z(sacc[2 * (jp)],     qa[0], f[0], f[1]); \
      mma_f16_z(sacc[2 * (jp) + 1], qa[0], f[2], f[3]); } \
    _Pragma("unroll") \
    for (int kk = 1; kk < 4; kk++) { \
        uint32_t f[4]; ldsm_x4(f, _kb + kk * 32); \
        mma_f16(sacc[2 * (jp)],     qa[kk], f[0], f[1]); \
        mma_f16(sacc[2 * (jp) + 1], qa[kk], f[2], f[3]); } \
} while (0)

// interleaved PV(tile kt, stage SC) and S(tile kt+1, stage SN)
#define BODY(ktv, SC, SN, SL, WAITM) do { \
    SOFTMAX(); \
    mwa = mrow0[(ktv) + 1] >> qs; \
    mwb = mrow1[(ktv) + 1] >> qs; \
    WAITM(); \
    __syncthreads(); \
    if ((ktv) + 3 < NTILE) ISSUE(SL, (ktv) + 3); \
    PV_HALF(SC, 0); \
    S_HALF(SN, 0); \
    PV_HALF(SC, 1); \
    S_HALF(SN, 1); \
} while (0)

    // ---- prologue: stage 3 tiles; S(0); ones-fragment loaded ONCE ----
    ISSUE(0, 0);
    ISSUE(1, 1);
    ISSUE(2, 2);
    CP_WAIT2();
    __syncthreads();
    mwa = mrow0[0] >> qs;
    mwb = mrow1[0] >> qs;
    ldsm_x2_t(fx, vbx);          // tile-invariant: same bytes in every stage
    S_HALF(0, 0);
    S_HALF(0, 1);

    // ---- 15 x 4 pipelined bodies (kt = 0..59) ----
    for (int kt = 0; kt < 60; kt += 4) {
        BODY(kt,     0, 1, 3, CP_WAIT1);
        BODY(kt + 1, 1, 2, 0, CP_WAIT1);
        BODY(kt + 2, 2, 3, 1, CP_WAIT1);
        BODY(kt + 3, 3, 0, 2, CP_WAIT1);
    }
    // ---- tail bodies 60..62 ----
    BODY(60, 0, 1, 3, CP_WAIT1);
    BODY(61, 1, 2, 0, CP_WAIT1);
    BODY(62, 2, 3, 1, CP_WAIT0);     // tile 63 must be fully resident

    // ---- epilogue: tile 63 (stage 3) ----
    SOFTMAX();
    PV_HALF(3, 0);
    PV_HALF(3, 1);

#undef BODY
#undef S_HALF
#undef PV_HALF
#undef SOFTMAX
#undef ISSUE

    // ---- lsum lives in ones-column block at qc==0; broadcast across quad ----
    const float l0 = __shfl_sync(0xFFFFFFFFu, oaccx[0], lane & 28);
    const float l1 = __shfl_sync(0xFFFFFFFFu, oaccx[2], lane & 28);
    const float inv0 = 1.0f / l0, inv1 = 1.0f / l1;

    float* o0 = Og + ((bh * Sc + qi0) << 6) + 2 * qc;
    float* o1 = Og + ((bh * Sc + qi1) << 6) + 2 * qc;
#pragma unroll
    for (int j = 0; j < 8; j++) {
        *reinterpret_cast<float2*>(o0 + j * 8) = make_float2(oacc[j][0] * inv0, oacc[j][1] * inv0);
        *reinterpret_cast<float2*>(o1 + j * 8) = make_float2(oacc[j][2] * inv1, oacc[j][3] * inv1);
    }
}

} // namespace

extern "C" void kernel_launch(void* const* d_in, const int* in_sizes, int n_in,
                              void* d_out, int out_size)
{
    const float* Q = (const float*)d_in[0];
    const float* K = (const float*)d_in[1];
    const float* V = (const float*)d_in[2];
    const int*   M = (const int*)d_in[3];
    float*       O = (float*)d_out;

    static int smem_set = 0;
    const int smem_bytes = NSTAGE * STAGE_BYTES;   // 36864
    if (!smem_set) {
        cudaFuncSetAttribute(attn_mma_kernel, cudaFuncAttributeMaxDynamicSharedMemorySize, smem_bytes);
        smem_set = 1;
    }

    prep_kernel<<<KVB + MB2, 256>>>(K, V, (const int4*)M);

    // PDL launch: main may launch while prep runs; griddepsync orders the data.
    cudaLaunchConfig_t cfg = {};
    cfg.gridDim = dim3(Sc / BM, Hc, Bc);
    cfg.blockDim = dim3(NT, 1, 1);
    cfg.dynamicSmemBytes = smem_bytes;
    cudaLaunchAttribute attrs[1];
    attrs[0].id = cudaLaunchAttributeProgrammaticStreamSerialization;
    attrs[0].val.programmaticStreamSerializationAllowed = 1;
    cfg.attrs = attrs;
    cfg.numAttrs = 1;
    cudaLaunchKernelEx(&cfg, attn_mma_kernel, Q, O);
}